// round 4
// baseline (speedup 1.0000x reference)
#include <cuda_runtime.h>
#include <cstddef>

#define BATCH 16
#define NPTS  1024
#define KNN   20
#define BN    (BATCH*NPTS)

typedef unsigned long long ull;

// ---------------- scratch (static device globals; allocation-free) ----------------
__device__ float g_hA[BN*256];
__device__ float g_hB[BN*256];
__device__ float g_u [BN*256];
__device__ float g_w [BN*256];
__device__ float g_ymax[BN*256];
__device__ float g_ymin[BN*256];
__device__ float g_xx[BN];
__device__ float g_dist[BATCH*NPTS*NPTS];     // 67 MB, L2-resident
__device__ int   g_idx[BN*KNN];
__device__ float g_ps[256*1024];              // stats partials [o][block]
__device__ float g_pq[256*1024];
__device__ float g_scale[256];
__device__ float g_shift[256];
__device__ float g_part[BATCH*16*256];

// ---------------- f32x2 helpers ----------------
__device__ __forceinline__ void fma2(ull& d, ull a, ull b) {
    asm("fma.rn.f32x2 %0, %1, %2, %0;" : "+l"(d) : "l"(a), "l"(b));
}
__device__ __forceinline__ float2 upk(ull v) {
    float2 f; asm("mov.b64 {%0,%1}, %2;" : "=f"(f.x), "=f"(f.y) : "l"(v)); return f;
}

// ---------------- prep: x (B,1,4,N) -> h (B,N,4) ----------------
__global__ void prep_kernel(const float* __restrict__ x, float* __restrict__ h) {
    int i = blockIdx.x*256 + threadIdx.x;          // over B*N*4
    int c = i & 3, n = (i >> 2) & (NPTS-1), b = i >> 12;
    h[i] = x[((size_t)b*4 + c)*NPTS + n];
}

// ---------------- xx[b,n] = |h_bn|^2 ----------------
template<int C>
__global__ void xx_kernel(const float* __restrict__ h, float* __restrict__ xx) {
    int i = blockIdx.x*256 + threadIdx.x;          // over B*N
    const float4* hp = (const float4*)(h + (size_t)i*C);
    float s = 0.f;
#pragma unroll
    for (int c = 0; c < C/4; c++) { float4 v = hp[c]; s += v.x*v.x + v.y*v.y + v.z*v.z + v.w*v.w; }
    xx[i] = s;
}

// ---------------- pairwise squared distances: 128x128 tile, 8x8/thread ----------------
template<int C>
__global__ __launch_bounds__(256) void dist_kernel(const float* __restrict__ h,
                                                   const float* __restrict__ xx,
                                                   float* __restrict__ dist) {
    constexpr int KC = (C >= 8) ? 8 : 4;
    __shared__ float As[KC][264];   // 128 rows duplicated pairs (256 floats) + pad
    __shared__ float Bs[KC][136];   // 128 floats + pad
    __shared__ float Ts[64][66];    // transpose staging (float2-aligned dump)
    int bx = blockIdx.x, by = blockIdx.y, b = blockIdx.z;
    if (bx > by) return;            // symmetry: compute lower triangle, mirror
    int n0 = by * 128, m0 = bx * 128;
    int tid = threadIdx.x;
    int tx = tid & 15, ty = tid >> 4;   // 16x16 threads, 8x8 values each
    ull acc[8][4];
#pragma unroll
    for (int i = 0; i < 8; i++)
#pragma unroll
        for (int j = 0; j < 4; j++) acc[i][j] = 0ull;
    const float* hb = h + (size_t)b*NPTS*C;
    for (int kk = 0; kk < C; kk += KC) {
        for (int e = tid; e < 128*KC; e += 256) {
            int r = e / KC, c = e % KC;
            float va = hb[(size_t)(n0 + r)*C + kk + c];
            As[c][2*r] = va; As[c][2*r+1] = va;
            Bs[c][r] = hb[(size_t)(m0 + r)*C + kk + c];
        }
        __syncthreads();
#pragma unroll
        for (int c = 0; c < KC; c++) {
            const ull* ap = (const ull*)&As[c][ty*16];
            const ull* bp = (const ull*)&Bs[c][tx*8];
            ull A[8], B[4];
#pragma unroll
            for (int i = 0; i < 8; i++) A[i] = ap[i];
#pragma unroll
            for (int j = 0; j < 4; j++) B[j] = bp[j];
#pragma unroll
            for (int i = 0; i < 8; i++)
#pragma unroll
                for (int j = 0; j < 4; j++) fma2(acc[i][j], A[i], B[j]);
        }
        __syncthreads();
    }
    const float* xxb = xx + b*NPTS;
    float xn[8], xm[8];
#pragma unroll
    for (int i = 0; i < 8; i++) { xn[i] = xxb[n0+ty*8+i]; xm[i] = xxb[m0+tx*8+i]; }
    float ov[8][8];
#pragma unroll
    for (int i = 0; i < 8; i++)
#pragma unroll
        for (int j = 0; j < 4; j++) {
            float2 p = upk(acc[i][j]);
            ov[i][2*j]   = xn[i] + xm[2*j]   - 2.f*p.x;
            ov[i][2*j+1] = xn[i] + xm[2*j+1] - 2.f*p.y;
        }
    float* db = dist + (size_t)b*NPTS*NPTS;
#pragma unroll
    for (int i = 0; i < 8; i++) {
        size_t off = (size_t)(n0+ty*8+i)*NPTS + m0 + tx*8;
        *(float4*)&db[off]   = make_float4(ov[i][0], ov[i][1], ov[i][2], ov[i][3]);
        *(float4*)&db[off+4] = make_float4(ov[i][4], ov[i][5], ov[i][6], ov[i][7]);
    }
    if (bx == by) return;
    // mirror: 4 sub-passes through a 64x64 smem transpose
#pragma unroll
    for (int sr = 0; sr < 2; sr++)
#pragma unroll
        for (int sc = 0; sc < 2; sc++) {
            __syncthreads();
            if ((ty >> 3) == sr && (tx >> 3) == sc) {
#pragma unroll
                for (int i = 0; i < 8; i++)
#pragma unroll
                    for (int j = 0; j < 8; j++)
                        Ts[(tx & 7)*8 + j][(ty & 7)*8 + i] = ov[i][j];
            }
            __syncthreads();
            for (int e = tid; e < 64*32; e += 256) {
                int r = e >> 5, c2 = (e & 31) * 2;
                float2 v = *(float2*)&Ts[r][c2];
                *(float2*)&db[(size_t)(m0 + sc*64 + r)*NPTS + n0 + sr*64 + c2] = v;
            }
        }
}

// ---------------- top-k=20: register-resident tournament, warp per row ----------------
// Lane owns leaves [lane*32, lane*32+32) in 8 float4 regs. Node (lane,g) covers
// leaves lane*32+g*8..+8, key = lane*4+g (key order == leaf-index order).
// Strict '<' everywhere -> lowest index wins ties (matches jax.lax.top_k).
__global__ __launch_bounds__(256) void topk_kernel(const float* __restrict__ dist,
                                                   int* __restrict__ idx) {
    int tid = threadIdx.x;
    int warp = tid >> 5, lane = tid & 31;
    int b = blockIdx.y;
    int n = blockIdx.x * 8 + warp;
    const float4* rp = (const float4*)(dist + ((size_t)b*NPTS + n)*NPTS + lane*32);
    float4 q[8];
#pragma unroll
    for (int j = 0; j < 8; j++) q[j] = rp[j];
    float nm[4];
#pragma unroll
    for (int g = 0; g < 4; g++) {
        float4 a = q[2*g], c = q[2*g+1];
        nm[g] = fminf(fminf(fminf(a.x,a.y), fminf(a.z,a.w)),
                      fminf(fminf(c.x,c.y), fminf(c.z,c.w)));
    }
    int* out = idx + ((size_t)b*NPTS + n)*KNN;
    for (int kk = 0; kk < KNN; kk++) {
        // 1) per-lane scan of node mins (ascending g, strict '<')
        float bv = nm[0]; int bg = 0;
#pragma unroll
        for (int g = 1; g < 4; g++) if (nm[g] < bv) { bv = nm[g]; bg = g; }
        int bk = lane*4 + bg;
        // 2) butterfly arg-reduce: result uniform on all lanes
#pragma unroll
        for (int off = 16; off; off >>= 1) {
            float ov = __shfl_xor_sync(0xffffffffu, bv, off);
            int   ok = __shfl_xor_sync(0xffffffffu, bk, off);
            if (ov < bv || (ov == bv && ok < bk)) { bv = ov; bk = ok; }
        }
        int wl = bk >> 2, wg = bk & 3;       // uniform
        // 3) every lane argmins its own group wg (uniform switch); only wl's matters
        float4 a, c;
        switch (wg) {
            case 0:  a = q[0]; c = q[1]; break;
            case 1:  a = q[2]; c = q[3]; break;
            case 2:  a = q[4]; c = q[5]; break;
            default: a = q[6]; c = q[7]; break;
        }
        float v[8] = {a.x, a.y, a.z, a.w, c.x, c.y, c.z, c.w};
        float mv = v[0]; int li = 0;
#pragma unroll
        for (int i = 1; i < 8; i++) if (v[i] < mv) { mv = v[i]; li = i; }
        int gli = __shfl_sync(0xffffffffu, li, wl);
        if (lane == 0) out[kk] = wl*32 + wg*8 + gli;
        // 4) owning lane invalidates the leaf and recomputes its node min
        if (lane == wl) {
#pragma unroll
            for (int i = 0; i < 8; i++) if (i == gli) v[i] = 3.4e38f;
            float m2 = fminf(fminf(fminf(v[0],v[1]), fminf(v[2],v[3])),
                             fminf(fminf(v[4],v[5]), fminf(v[6],v[7])));
            float4 na = make_float4(v[0],v[1],v[2],v[3]);
            float4 nc = make_float4(v[4],v[5],v[6],v[7]);
            switch (wg) {
                case 0:  q[0] = na; q[1] = nc; nm[0] = m2; break;
                case 1:  q[2] = na; q[3] = nc; nm[1] = m2; break;
                case 2:  q[4] = na; q[5] = nc; nm[2] = m2; break;
                default: q[6] = na; q[7] = nc; nm[3] = m2; break;
            }
        }
    }
}

// ---------------- u = h W1^T, w = h (W2-W1)^T  (f32x2-tiled) ----------------
template<int C, int O>
__global__ __launch_bounds__(256) void gemm_kernel(const float* __restrict__ h,
                                                   const float* __restrict__ W,
                                                   float* __restrict__ u,
                                                   float* __restrict__ w) {
    constexpr int KC = (C >= 8) ? 8 : 4;
    __shared__ float As[KC][144];
    __shared__ float B1[KC][72];
    __shared__ float B2[KC][72];
    int o0 = blockIdx.x * 64;
    int r0 = blockIdx.y * 64;
    int tid = threadIdx.x, tx = tid & 15, ty = tid >> 4;
    ull au[4][2], aw[4][2];
#pragma unroll
    for (int i = 0; i < 4; i++) { au[i][0]=0ull; au[i][1]=0ull; aw[i][0]=0ull; aw[i][1]=0ull; }
    for (int kk = 0; kk < C; kk += KC) {
#pragma unroll
        for (int t = 0; t < (64*KC)/256; t++) {
            int e = tid + t*256;
            int r = e / KC, c = e % KC;
            float va = h[(size_t)(r0 + r)*C + kk + c];
            *(float2*)&As[c][2*r] = make_float2(va, va);
            float w1 = W[(size_t)(o0 + r)*(2*C) + kk + c];
            float w2 = W[(size_t)(o0 + r)*(2*C) + C + kk + c];
            B1[c][r] = w1;
            B2[c][r] = w2 - w1;
        }
        __syncthreads();
#pragma unroll
        for (int c = 0; c < KC; c++) {
            ull a0 = *(const ull*)&As[c][(ty*4+0)*2];
            ull a1 = *(const ull*)&As[c][(ty*4+1)*2];
            ull a2 = *(const ull*)&As[c][(ty*4+2)*2];
            ull a3 = *(const ull*)&As[c][(ty*4+3)*2];
            ull p0 = *(const ull*)&B1[c][tx*4];
            ull p1 = *(const ull*)&B1[c][tx*4+2];
            ull q0 = *(const ull*)&B2[c][tx*4];
            ull q1 = *(const ull*)&B2[c][tx*4+2];
            fma2(au[0][0],a0,p0); fma2(au[0][1],a0,p1);
            fma2(au[1][0],a1,p0); fma2(au[1][1],a1,p1);
            fma2(au[2][0],a2,p0); fma2(au[2][1],a2,p1);
            fma2(au[3][0],a3,p0); fma2(au[3][1],a3,p1);
            fma2(aw[0][0],a0,q0); fma2(aw[0][1],a0,q1);
            fma2(aw[1][0],a1,q0); fma2(aw[1][1],a1,q1);
            fma2(aw[2][0],a2,q0); fma2(aw[2][1],a2,q1);
            fma2(aw[3][0],a3,q0); fma2(aw[3][1],a3,q1);
        }
        __syncthreads();
    }
#pragma unroll
    for (int i = 0; i < 4; i++) {
        float2 u0 = upk(au[i][0]), u1 = upk(au[i][1]);
        float2 v0 = upk(aw[i][0]), v1 = upk(aw[i][1]);
        size_t off = (size_t)(r0 + ty*4 + i)*O + o0 + tx*4;
        *(float4*)&u[off] = make_float4(u0.x, u0.y, u1.x, u1.y);
        *(float4*)&w[off] = make_float4(v0.x, v0.y, v1.x, v1.y);
    }
}

// ---------------- single gather pass: sums, sumsq, per-(n,o) ymax/ymin ----------------
template<int O>
__global__ void stats_kernel(const float* __restrict__ u, const float* __restrict__ w,
                             const int* __restrict__ idx,
                             float* __restrict__ ps, float* __restrict__ pq,
                             float* __restrict__ ymax, float* __restrict__ ymin) {
    __shared__ int idxs[16*KNN];
    int blk = blockIdx.x;
    int node0 = blk * 16;
    int o = threadIdx.x;
    for (int e = threadIdx.x; e < 16*KNN; e += O) idxs[e] = idx[(size_t)node0*KNN + e];
    __syncthreads();
    const float* ub = u + (size_t)(node0 & ~(NPTS-1))*O;   // batch base
    float s = 0.f, q = 0.f;
    for (int n = 0; n < 16; n++) {
        float wv = w[(size_t)(node0 + n)*O + o];
        float mx = -3.4e38f, mn = 3.4e38f;
#pragma unroll
        for (int kk = 0; kk < KNN; kk++) {
            float y = ub[(size_t)idxs[n*KNN + kk]*O + o] + wv;
            s += y; q += y*y;
            mx = fmaxf(mx, y); mn = fminf(mn, y);
        }
        ymax[(size_t)(node0 + n)*O + o] = mx;
        ymin[(size_t)(node0 + n)*O + o] = mn;
    }
    ps[(size_t)o*1024 + blk] = s;
    pq[(size_t)o*1024 + blk] = q;
}

// ---------------- reduce partials -> scale/shift per channel ----------------
__global__ void bnstats_kernel(const float* __restrict__ ps, const float* __restrict__ pq,
                               const float* __restrict__ g, const float* __restrict__ bt,
                               float* __restrict__ scale, float* __restrict__ shift) {
    int o = blockIdx.x*8 + (threadIdx.x >> 5);
    int lane = threadIdx.x & 31;
    float s = 0.f, q = 0.f;
    for (int p = lane; p < 1024; p += 32) { s += ps[(size_t)o*1024 + p]; q += pq[(size_t)o*1024 + p]; }
#pragma unroll
    for (int off = 16; off; off >>= 1) {
        s += __shfl_down_sync(0xffffffffu, s, off);
        q += __shfl_down_sync(0xffffffffu, q, off);
    }
    if (lane == 0) {
        const float inv = 1.f / (float)(BATCH*NPTS*KNN);
        float mean = s * inv;
        float var  = q * inv - mean*mean;
        float rs   = rsqrtf(var + 1e-5f);
        float sc   = g[o] * rs;
        scale[o] = sc;
        shift[o] = bt[o] - mean*sc;
    }
}

// ---------------- finalize: BN + LeakyReLU on the k-extremum (monotone trick) ----------------
template<int O>
__global__ void finalize_kernel(const float* __restrict__ ymax, const float* __restrict__ ymin,
                                const float* __restrict__ scale, const float* __restrict__ shift,
                                float* __restrict__ hout) {
    int i = blockIdx.x*256 + threadIdx.x;           // over BN*O
    int o = i & (O-1);
    float sc = scale[o];
    float y  = (sc >= 0.f) ? ymax[i] : ymin[i];
    float v  = y*sc + shift[o];
    hout[i] = (v >= 0.f) ? v : 0.2f*v;
}

// ---------------- final max over N (two deterministic stages) ----------------
__global__ void pmax_kernel(const float* __restrict__ h, float* __restrict__ part) {
    int b = blockIdx.y, ch = blockIdx.x, o = threadIdx.x;
    const float* hp = h + ((size_t)b*NPTS + ch*64)*256 + o;
    float m = -3.4e38f;
    for (int n = 0; n < 64; n++) m = fmaxf(m, hp[(size_t)n*256]);
    part[((size_t)b*16 + ch)*256 + o] = m;
}
__global__ void fmax_kernel(const float* __restrict__ part, float* __restrict__ out) {
    int b = blockIdx.x, o = threadIdx.x;
    float m = -3.4e38f;
    for (int c = 0; c < 16; c++) m = fmaxf(m, part[((size_t)b*16 + c)*256 + o]);
    out[(size_t)b*256 + o] = m;
}

// ---------------- host orchestration ----------------
struct Scratch {
    float *hA, *hB, *u, *w, *ymax, *ymin, *xx, *dist, *ps, *pq, *scale, *shift, *part;
    int* idx;
};

template<int C, int O>
static void run_layer(const float* hin, float* hout, const float* W,
                      const float* g, const float* bt, const Scratch& Z) {
    xx_kernel<C><<<BN/256, 256>>>(hin, Z.xx);
    dist_kernel<C><<<dim3(8, 8, BATCH), 256>>>(hin, Z.xx, Z.dist);
    topk_kernel<<<dim3(NPTS/8, BATCH), 256>>>(Z.dist, Z.idx);
    gemm_kernel<C, O><<<dim3(O/64, BN/64), 256>>>(hin, W, Z.u, Z.w);
    stats_kernel<O><<<BN/16, O>>>(Z.u, Z.w, Z.idx, Z.ps, Z.pq, Z.ymax, Z.ymin);
    bnstats_kernel<<<O/8, 256>>>(Z.ps, Z.pq, g, bt, Z.scale, Z.shift);
    finalize_kernel<O><<<(BN*O)/256, 256>>>(Z.ymax, Z.ymin, Z.scale, Z.shift, hout);
}

extern "C" void kernel_launch(void* const* d_in, const int* in_sizes, int n_in,
                              void* d_out, int out_size) {
    const float* x = (const float*)d_in[0];
    const float* Wp[4]; const float* gp[4]; const float* bp[4];
    for (int i = 0; i < 4; i++) {
        Wp[i] = (const float*)d_in[1 + 3*i];
        gp[i] = (const float*)d_in[2 + 3*i];
        bp[i] = (const float*)d_in[3 + 3*i];
    }
    Scratch Z;
    cudaGetSymbolAddress((void**)&Z.hA,    g_hA);
    cudaGetSymbolAddress((void**)&Z.hB,    g_hB);
    cudaGetSymbolAddress((void**)&Z.u,     g_u);
    cudaGetSymbolAddress((void**)&Z.w,     g_w);
    cudaGetSymbolAddress((void**)&Z.ymax,  g_ymax);
    cudaGetSymbolAddress((void**)&Z.ymin,  g_ymin);
    cudaGetSymbolAddress((void**)&Z.xx,    g_xx);
    cudaGetSymbolAddress((void**)&Z.dist,  g_dist);
    cudaGetSymbolAddress((void**)&Z.ps,    g_ps);
    cudaGetSymbolAddress((void**)&Z.pq,    g_pq);
    cudaGetSymbolAddress((void**)&Z.scale, g_scale);
    cudaGetSymbolAddress((void**)&Z.shift, g_shift);
    cudaGetSymbolAddress((void**)&Z.part,  g_part);
    cudaGetSymbolAddress((void**)&Z.idx,   g_idx);

    prep_kernel<<<(BN*4)/256, 256>>>(x, Z.hA);

    run_layer<4,   64 >(Z.hA, Z.hB, Wp[0], gp[0], bp[0], Z);
    run_layer<64,  64 >(Z.hB, Z.hA, Wp[1], gp[1], bp[1], Z);
    run_layer<64,  128>(Z.hA, Z.hB, Wp[2], gp[2], bp[2], Z);
    run_layer<128, 256>(Z.hB, Z.hA, Wp[3], gp[3], bp[3], Z);

    pmax_kernel<<<dim3(16, BATCH), 256>>>(Z.hA, Z.part);
    fmax_kernel<<<BATCH, 256>>>(Z.part, (float*)d_out);
}

// round 5
// speedup vs baseline: 1.1908x; 1.1908x over previous
#include <cuda_runtime.h>
#include <cstddef>

#define BATCH 16
#define NPTS  1024
#define KNN   20
#define BN    (BATCH*NPTS)

typedef unsigned long long ull;

// ---------------- scratch (static device globals; allocation-free) ----------------
__device__ float g_hA[BN*256];
__device__ float g_hB[BN*256];
__device__ float g_u [BN*256];
__device__ float g_w [BN*256];
__device__ float g_ymax[BN*256];
__device__ float g_ymin[BN*256];
__device__ float g_xx[BN];
__device__ float g_dist[BATCH*NPTS*NPTS];     // 67 MB, L2-resident
__device__ int   g_idx[BN*KNN];
__device__ float g_ps[256*1024];              // stats partials [o][block]
__device__ float g_pq[256*1024];
__device__ float g_scale[256];
__device__ float g_shift[256];
__device__ float g_part[BATCH*16*256];

// ---------------- f32x2 helpers ----------------
__device__ __forceinline__ void fma2(ull& d, ull a, ull b) {
    asm("fma.rn.f32x2 %0, %1, %2, %0;" : "+l"(d) : "l"(a), "l"(b));
}
__device__ __forceinline__ float2 upk(ull v) {
    float2 f; asm("mov.b64 {%0,%1}, %2;" : "=f"(f.x), "=f"(f.y) : "l"(v)); return f;
}
__device__ __forceinline__ unsigned redux_min_u32(unsigned v) {
    unsigned r; asm("redux.sync.min.u32 %0, %1, 0xffffffff;" : "=r"(r) : "r"(v)); return r;
}
__device__ __forceinline__ int redux_min_s32(int v) {
    int r; asm("redux.sync.min.s32 %0, %1, 0xffffffff;" : "=r"(r) : "r"(v)); return r;
}

// ---------------- prep: x (B,1,4,N) -> h (B,N,4) ----------------
__global__ void prep_kernel(const float* __restrict__ x, float* __restrict__ h) {
    int i = blockIdx.x*256 + threadIdx.x;          // over B*N*4
    int c = i & 3, n = (i >> 2) & (NPTS-1), b = i >> 12;
    h[i] = x[((size_t)b*4 + c)*NPTS + n];
}

// ---------------- xx[b,n] = |h_bn|^2 ----------------
template<int C>
__global__ void xx_kernel(const float* __restrict__ h, float* __restrict__ xx) {
    int i = blockIdx.x*256 + threadIdx.x;          // over B*N
    const float4* hp = (const float4*)(h + (size_t)i*C);
    float s = 0.f;
#pragma unroll
    for (int c = 0; c < C/4; c++) { float4 v = hp[c]; s += v.x*v.x + v.y*v.y + v.z*v.z + v.w*v.w; }
    xx[i] = s;
}

// ---------------- pairwise squared distances: 128x128 tile, 8x8/thread ----------------
template<int C>
__global__ __launch_bounds__(256) void dist_kernel(const float* __restrict__ h,
                                                   const float* __restrict__ xx,
                                                   float* __restrict__ dist) {
    constexpr int KC = (C >= 8) ? 8 : 4;
    __shared__ float As[KC][264];   // 128 rows duplicated pairs (256 floats) + pad
    __shared__ float Bs[KC][136];   // 128 floats + pad
    __shared__ float Ts[64][66];    // transpose staging (float2-aligned dump)
    int bx = blockIdx.x, by = blockIdx.y, b = blockIdx.z;
    if (bx > by) return;            // symmetry: compute lower triangle, mirror
    int n0 = by * 128, m0 = bx * 128;
    int tid = threadIdx.x;
    int tx = tid & 15, ty = tid >> 4;   // 16x16 threads, 8x8 values each
    ull acc[8][4];
#pragma unroll
    for (int i = 0; i < 8; i++)
#pragma unroll
        for (int j = 0; j < 4; j++) acc[i][j] = 0ull;
    const float* hb = h + (size_t)b*NPTS*C;
    for (int kk = 0; kk < C; kk += KC) {
        for (int e = tid; e < 128*KC; e += 256) {
            int r = e / KC, c = e % KC;
            float va = hb[(size_t)(n0 + r)*C + kk + c];
            As[c][2*r] = va; As[c][2*r+1] = va;
            Bs[c][r] = hb[(size_t)(m0 + r)*C + kk + c];
        }
        __syncthreads();
#pragma unroll
        for (int c = 0; c < KC; c++) {
            const ull* ap = (const ull*)&As[c][ty*16];
            const ull* bp = (const ull*)&Bs[c][tx*8];
            ull A[8], B[4];
#pragma unroll
            for (int i = 0; i < 8; i++) A[i] = ap[i];
#pragma unroll
            for (int j = 0; j < 4; j++) B[j] = bp[j];
#pragma unroll
            for (int i = 0; i < 8; i++)
#pragma unroll
                for (int j = 0; j < 4; j++) fma2(acc[i][j], A[i], B[j]);
        }
        __syncthreads();
    }
    const float* xxb = xx + b*NPTS;
    float xn[8], xm[8];
#pragma unroll
    for (int i = 0; i < 8; i++) { xn[i] = xxb[n0+ty*8+i]; xm[i] = xxb[m0+tx*8+i]; }
    float ov[8][8];
#pragma unroll
    for (int i = 0; i < 8; i++)
#pragma unroll
        for (int j = 0; j < 4; j++) {
            float2 p = upk(acc[i][j]);
            ov[i][2*j]   = xn[i] + xm[2*j]   - 2.f*p.x;
            ov[i][2*j+1] = xn[i] + xm[2*j+1] - 2.f*p.y;
        }
    float* db = dist + (size_t)b*NPTS*NPTS;
#pragma unroll
    for (int i = 0; i < 8; i++) {
        size_t off = (size_t)(n0+ty*8+i)*NPTS + m0 + tx*8;
        *(float4*)&db[off]   = make_float4(ov[i][0], ov[i][1], ov[i][2], ov[i][3]);
        *(float4*)&db[off+4] = make_float4(ov[i][4], ov[i][5], ov[i][6], ov[i][7]);
    }
    if (bx == by) return;
    // mirror: 4 sub-passes through a 64x64 smem transpose
#pragma unroll
    for (int sr = 0; sr < 2; sr++)
#pragma unroll
        for (int sc = 0; sc < 2; sc++) {
            __syncthreads();
            if ((ty >> 3) == sr && (tx >> 3) == sc) {
#pragma unroll
                for (int i = 0; i < 8; i++)
#pragma unroll
                    for (int j = 0; j < 8; j++)
                        Ts[(tx & 7)*8 + j][(ty & 7)*8 + i] = ov[i][j];
            }
            __syncthreads();
            for (int e = tid; e < 64*32; e += 256) {
                int r = e >> 5, c2 = (e & 31) * 2;
                float2 v = *(float2*)&Ts[r][c2];
                *(float2*)&db[(size_t)(m0 + sc*64 + r)*NPTS + n0 + sr*64 + c2] = v;
            }
        }
}

// ---------------- top-k=20: redux-based tournament, warp per row ----------------
// Row staged in smem as 256 float4 chunks; lane owns chunks {c : c%32==lane}
// (8 chunks -> 32 leaves), node g covers its chunks 2g,2g+1. All LDS/STS
// conflict-free. Selection per round:
//   1) lane-min over nm[4]                       (3 fmin)
//   2) redux.sync.min.u32 on order-mapped bits   (1 instr)
//   3) matching lanes locate their lowest index  (predicated, ~1 lane)
//   4) redux.sync.min.s32 on candidate index     (exact lowest-index tie-break)
//   5) unique winner writes out, invalidates leaf, recomputes nm[g]
// Set semantics match jax.lax.top_k (downstream reductions are order-invariant).
__global__ __launch_bounds__(256) void topk_kernel(const float* __restrict__ dist,
                                                   int* __restrict__ idx) {
    __shared__ float4 ds[8][256];
    int b = blockIdx.y, n0 = blockIdx.x * 8;
    int tid = threadIdx.x;
    const float4* src = (const float4*)(dist + ((size_t)b*NPTS + n0)*NPTS);
    float4* flat = &ds[0][0];
    for (int e = tid; e < 8*256; e += 256) flat[e] = src[e];
    __syncthreads();
    int wr = tid >> 5, lane = tid & 31;
    float4* rowc = ds[wr];
    float*  rowf = (float*)rowc;
    float nm[4];
#pragma unroll
    for (int g = 0; g < 4; g++) {
        float4 a = rowc[(2*g)*32 + lane];
        float4 c = rowc[(2*g+1)*32 + lane];
        nm[g] = fminf(fminf(fminf(a.x,a.y), fminf(a.z,a.w)),
                      fminf(fminf(c.x,c.y), fminf(c.z,c.w)));
    }
    int* out = idx + ((size_t)b*NPTS + n0 + wr)*KNN;
    for (int kk = 0; kk < KNN; kk++) {
        float lm = fminf(fminf(nm[0], nm[1]), fminf(nm[2], nm[3]));
        unsigned bu = __float_as_uint(lm);
        unsigned tu = bu ^ (((unsigned)((int)bu >> 31)) | 0x80000000u);
        unsigned gm = redux_min_u32(tu);
        int mym = 0x7FFFFFFF;
        int g = 0, li = 0;
        float v[8];
        if (tu == gm) {
            g = (nm[0]==lm) ? 0 : (nm[1]==lm) ? 1 : (nm[2]==lm) ? 2 : 3;
            float4 a = rowc[(2*g)*32 + lane];
            float4 c = rowc[(2*g+1)*32 + lane];
            v[0]=a.x; v[1]=a.y; v[2]=a.z; v[3]=a.w;
            v[4]=c.x; v[5]=c.y; v[6]=c.z; v[7]=c.w;
            li = 7;
#pragma unroll
            for (int i = 6; i >= 0; i--) if (v[i] == lm) li = i;   // lowest i
            mym = g*256 + ((li >= 4) ? 128 : 0) + lane*4 + (li & 3);
        }
        int mwin = redux_min_s32(mym);            // lowest global index among ties
        if (mym == mwin) {
            out[kk] = mwin;
            rowf[((2*g + (li >> 2))*32 + lane)*4 + (li & 3)] = 3.4e38f;
#pragma unroll
            for (int i = 0; i < 8; i++) if (i == li) v[i] = 3.4e38f;
            nm[g] = fminf(fminf(fminf(v[0],v[1]), fminf(v[2],v[3])),
                          fminf(fminf(v[4],v[5]), fminf(v[6],v[7])));
        }
    }
}

// ---------------- u = h W1^T, w = h (W2-W1)^T  (f32x2-tiled) ----------------
template<int C, int O>
__global__ __launch_bounds__(256) void gemm_kernel(const float* __restrict__ h,
                                                   const float* __restrict__ W,
                                                   float* __restrict__ u,
                                                   float* __restrict__ w) {
    constexpr int KC = (C >= 8) ? 8 : 4;
    __shared__ float As[KC][144];
    __shared__ float B1[KC][72];
    __shared__ float B2[KC][72];
    int o0 = blockIdx.x * 64;
    int r0 = blockIdx.y * 64;
    int tid = threadIdx.x, tx = tid & 15, ty = tid >> 4;
    ull au[4][2], aw[4][2];
#pragma unroll
    for (int i = 0; i < 4; i++) { au[i][0]=0ull; au[i][1]=0ull; aw[i][0]=0ull; aw[i][1]=0ull; }
    for (int kk = 0; kk < C; kk += KC) {
#pragma unroll
        for (int t = 0; t < (64*KC)/256; t++) {
            int e = tid + t*256;
            int r = e / KC, c = e % KC;
            float va = h[(size_t)(r0 + r)*C + kk + c];
            *(float2*)&As[c][2*r] = make_float2(va, va);
            float w1 = W[(size_t)(o0 + r)*(2*C) + kk + c];
            float w2 = W[(size_t)(o0 + r)*(2*C) + C + kk + c];
            B1[c][r] = w1;
            B2[c][r] = w2 - w1;
        }
        __syncthreads();
#pragma unroll
        for (int c = 0; c < KC; c++) {
            ull a0 = *(const ull*)&As[c][(ty*4+0)*2];
            ull a1 = *(const ull*)&As[c][(ty*4+1)*2];
            ull a2 = *(const ull*)&As[c][(ty*4+2)*2];
            ull a3 = *(const ull*)&As[c][(ty*4+3)*2];
            ull p0 = *(const ull*)&B1[c][tx*4];
            ull p1 = *(const ull*)&B1[c][tx*4+2];
            ull q0 = *(const ull*)&B2[c][tx*4];
            ull q1 = *(const ull*)&B2[c][tx*4+2];
            fma2(au[0][0],a0,p0); fma2(au[0][1],a0,p1);
            fma2(au[1][0],a1,p0); fma2(au[1][1],a1,p1);
            fma2(au[2][0],a2,p0); fma2(au[2][1],a2,p1);
            fma2(au[3][0],a3,p0); fma2(au[3][1],a3,p1);
            fma2(aw[0][0],a0,q0); fma2(aw[0][1],a0,q1);
            fma2(aw[1][0],a1,q0); fma2(aw[1][1],a1,q1);
            fma2(aw[2][0],a2,q0); fma2(aw[2][1],a2,q1);
            fma2(aw[3][0],a3,q0); fma2(aw[3][1],a3,q1);
        }
        __syncthreads();
    }
#pragma unroll
    for (int i = 0; i < 4; i++) {
        float2 u0 = upk(au[i][0]), u1 = upk(au[i][1]);
        float2 v0 = upk(aw[i][0]), v1 = upk(aw[i][1]);
        size_t off = (size_t)(r0 + ty*4 + i)*O + o0 + tx*4;
        *(float4*)&u[off] = make_float4(u0.x, u0.y, u1.x, u1.y);
        *(float4*)&w[off] = make_float4(v0.x, v0.y, v1.x, v1.y);
    }
}

// ---------------- single gather pass: sums, sumsq, per-(n,o) ymax/ymin ----------------
template<int O>
__global__ void stats_kernel(const float* __restrict__ u, const float* __restrict__ w,
                             const int* __restrict__ idx,
                             float* __restrict__ ps, float* __restrict__ pq,
                             float* __restrict__ ymax, float* __restrict__ ymin) {
    __shared__ int idxs[16*KNN];
    int blk = blockIdx.x;
    int node0 = blk * 16;
    int o = threadIdx.x;
    for (int e = threadIdx.x; e < 16*KNN; e += O) idxs[e] = idx[(size_t)node0*KNN + e];
    __syncthreads();
    const float* ub = u + (size_t)(node0 & ~(NPTS-1))*O;   // batch base
    float s = 0.f, q = 0.f;
    for (int n = 0; n < 16; n++) {
        float wv = w[(size_t)(node0 + n)*O + o];
        float mx = -3.4e38f, mn = 3.4e38f;
#pragma unroll
        for (int kk = 0; kk < KNN; kk++) {
            float y = ub[(size_t)idxs[n*KNN + kk]*O + o] + wv;
            s += y; q += y*y;
            mx = fmaxf(mx, y); mn = fminf(mn, y);
        }
        ymax[(size_t)(node0 + n)*O + o] = mx;
        ymin[(size_t)(node0 + n)*O + o] = mn;
    }
    ps[(size_t)o*1024 + blk] = s;
    pq[(size_t)o*1024 + blk] = q;
}

// ---------------- reduce partials -> scale/shift per channel ----------------
__global__ void bnstats_kernel(const float* __restrict__ ps, const float* __restrict__ pq,
                               const float* __restrict__ g, const float* __restrict__ bt,
                               float* __restrict__ scale, float* __restrict__ shift) {
    int o = blockIdx.x*8 + (threadIdx.x >> 5);
    int lane = threadIdx.x & 31;
    float s = 0.f, q = 0.f;
    for (int p = lane; p < 1024; p += 32) { s += ps[(size_t)o*1024 + p]; q += pq[(size_t)o*1024 + p]; }
#pragma unroll
    for (int off = 16; off; off >>= 1) {
        s += __shfl_down_sync(0xffffffffu, s, off);
        q += __shfl_down_sync(0xffffffffu, q, off);
    }
    if (lane == 0) {
        const float inv = 1.f / (float)(BATCH*NPTS*KNN);
        float mean = s * inv;
        float var  = q * inv - mean*mean;
        float rs   = rsqrtf(var + 1e-5f);
        float sc   = g[o] * rs;
        scale[o] = sc;
        shift[o] = bt[o] - mean*sc;
    }
}

// ---------------- finalize: BN + LeakyReLU on the k-extremum (monotone trick) ----------------
template<int O>
__global__ void finalize_kernel(const float* __restrict__ ymax, const float* __restrict__ ymin,
                                const float* __restrict__ scale, const float* __restrict__ shift,
                                float* __restrict__ hout) {
    int i = blockIdx.x*256 + threadIdx.x;           // over BN*O
    int o = i & (O-1);
    float sc = scale[o];
    float y  = (sc >= 0.f) ? ymax[i] : ymin[i];
    float v  = y*sc + shift[o];
    hout[i] = (v >= 0.f) ? v : 0.2f*v;
}

// ---------------- final max over N (two deterministic stages) ----------------
__global__ void pmax_kernel(const float* __restrict__ h, float* __restrict__ part) {
    int b = blockIdx.y, ch = blockIdx.x, o = threadIdx.x;
    const float* hp = h + ((size_t)b*NPTS + ch*64)*256 + o;
    float m = -3.4e38f;
    for (int n = 0; n < 64; n++) m = fmaxf(m, hp[(size_t)n*256]);
    part[((size_t)b*16 + ch)*256 + o] = m;
}
__global__ void fmax_kernel(const float* __restrict__ part, float* __restrict__ out) {
    int b = blockIdx.x, o = threadIdx.x;
    float m = -3.4e38f;
    for (int c = 0; c < 16; c++) m = fmaxf(m, part[((size_t)b*16 + c)*256 + o]);
    out[(size_t)b*256 + o] = m;
}

// ---------------- host orchestration ----------------
struct Scratch {
    float *hA, *hB, *u, *w, *ymax, *ymin, *xx, *dist, *ps, *pq, *scale, *shift, *part;
    int* idx;
};

template<int C, int O>
static void run_layer(const float* hin, float* hout, const float* W,
                      const float* g, const float* bt, const Scratch& Z) {
    xx_kernel<C><<<BN/256, 256>>>(hin, Z.xx);
    dist_kernel<C><<<dim3(8, 8, BATCH), 256>>>(hin, Z.xx, Z.dist);
    topk_kernel<<<dim3(NPTS/8, BATCH), 256>>>(Z.dist, Z.idx);
    gemm_kernel<C, O><<<dim3(O/64, BN/64), 256>>>(hin, W, Z.u, Z.w);
    stats_kernel<O><<<BN/16, O>>>(Z.u, Z.w, Z.idx, Z.ps, Z.pq, Z.ymax, Z.ymin);
    bnstats_kernel<<<O/8, 256>>>(Z.ps, Z.pq, g, bt, Z.scale, Z.shift);
    finalize_kernel<O><<<(BN*O)/256, 256>>>(Z.ymax, Z.ymin, Z.scale, Z.shift, hout);
}

extern "C" void kernel_launch(void* const* d_in, const int* in_sizes, int n_in,
                              void* d_out, int out_size) {
    const float* x = (const float*)d_in[0];
    const float* Wp[4]; const float* gp[4]; const float* bp[4];
    for (int i = 0; i < 4; i++) {
        Wp[i] = (const float*)d_in[1 + 3*i];
        gp[i] = (const float*)d_in[2 + 3*i];
        bp[i] = (const float*)d_in[3 + 3*i];
    }
    Scratch Z;
    cudaGetSymbolAddress((void**)&Z.hA,    g_hA);
    cudaGetSymbolAddress((void**)&Z.hB,    g_hB);
    cudaGetSymbolAddress((void**)&Z.u,     g_u);
    cudaGetSymbolAddress((void**)&Z.w,     g_w);
    cudaGetSymbolAddress((void**)&Z.ymax,  g_ymax);
    cudaGetSymbolAddress((void**)&Z.ymin,  g_ymin);
    cudaGetSymbolAddress((void**)&Z.xx,    g_xx);
    cudaGetSymbolAddress((void**)&Z.dist,  g_dist);
    cudaGetSymbolAddress((void**)&Z.ps,    g_ps);
    cudaGetSymbolAddress((void**)&Z.pq,    g_pq);
    cudaGetSymbolAddress((void**)&Z.scale, g_scale);
    cudaGetSymbolAddress((void**)&Z.shift, g_shift);
    cudaGetSymbolAddress((void**)&Z.part,  g_part);
    cudaGetSymbolAddress((void**)&Z.idx,   g_idx);

    prep_kernel<<<(BN*4)/256, 256>>>(x, Z.hA);

    run_layer<4,   64 >(Z.hA, Z.hB, Wp[0], gp[0], bp[0], Z);
    run_layer<64,  64 >(Z.hB, Z.hA, Wp[1], gp[1], bp[1], Z);
    run_layer<64,  128>(Z.hA, Z.hB, Wp[2], gp[2], bp[2], Z);
    run_layer<128, 256>(Z.hB, Z.hA, Wp[3], gp[3], bp[3], Z);

    pmax_kernel<<<dim3(16, BATCH), 256>>>(Z.hA, Z.part);
    fmax_kernel<<<BATCH, 256>>>(Z.part, (float*)d_out);
}